// round 2
// baseline (speedup 1.0000x reference)
#include <cuda_runtime.h>
#include <cstdint>

// out[idx] = (Pid[idx] > 0) ? 1.f : 0.f, replicated into `ncopies` output halves.
// float4 vectorized: N = B*V*V = 67,108,864 is divisible by 4.
__global__ void binarize_dup_kernel(const float4* __restrict__ pid,
                                    float4* __restrict__ out,
                                    long long n4, long long half4, int ncopies) {
    long long i = (long long)blockIdx.x * blockDim.x + threadIdx.x;
    if (i >= n4) return;
    float4 p = pid[i];
    float4 v;
    v.x = p.x > 0.f ? 1.f : 0.f;
    v.y = p.y > 0.f ? 1.f : 0.f;
    v.z = p.z > 0.f ? 1.f : 0.f;
    v.w = p.w > 0.f ? 1.f : 0.f;
    out[i] = v;
    if (ncopies > 1) out[i + half4] = v;
}

// Per-batch fixup: predicates read the ORIGINAL Pid (all pre-edit in the
// reference), and the 8 edited positions are pairwise distinct when valid,
// so this can run as a tiny pass after the binarize.
__global__ void fixup_kernel(const float* __restrict__ pid,
                             const int* __restrict__ inter,
                             float* __restrict__ out,
                             int B, int V, long long half, int ncopies) {
    int b = blockIdx.x * blockDim.x + threadIdx.x;
    if (b >= B) return;
    int e10 = inter[b * 4 + 0];
    int e11 = inter[b * 4 + 1];
    int e20 = inter[b * 4 + 2];
    int e21 = inter[b * 4 + 3];

    bool distinct = (e10 != e11) && (e10 != e20) && (e10 != e21) &&
                    (e11 != e20) && (e11 != e21) && (e20 != e21);
    if (!distinct) return;

    long long base = (long long)b * V * V;
    bool blocked = (pid[base + (long long)e10 * V + e20] > 0.f) ||
                   (pid[base + (long long)e11 * V + e21] > 0.f);
    if (blocked) return;

    float old_pid = (pid[base + (long long)e10 * V + e11] > 0.f) ? 1.f : 0.f;

    for (int c = 0; c < ncopies; c++) {
        float* o = out + base + (long long)c * half;
        o[(long long)e10 * V + e11] = 0.f;
        o[(long long)e11 * V + e10] = 0.f;
        o[(long long)e20 * V + e21] = 0.f;
        o[(long long)e21 * V + e20] = 0.f;
        o[(long long)e10 * V + e20] = old_pid;
        o[(long long)e20 * V + e10] = old_pid;
        o[(long long)e11 * V + e21] = 1.f;
        o[(long long)e21 * V + e11] = 1.f;
    }
}

extern "C" void kernel_launch(void* const* d_in, const int* in_sizes, int n_in,
                              void* d_out, int out_size) {
    const float* pid  = (const float*)d_in[0];   // (B, V, V) float32
    const int* inter  = (const int*)d_in[1];     // (B, 2, 2) int32
    float* out = (float*)d_out;

    const int V = 512;
    long long N = (long long)in_sizes[0];        // B*V*V
    int B = (int)(N / ((long long)V * V));       // 256
    int ncopies = (int)((long long)out_size / N);  // expect 2 (reference returns (out, out))
    if (ncopies < 1) ncopies = 1;

    long long n4 = N / 4;
    int threads = 256;
    long long blocks = (n4 + threads - 1) / threads;

    binarize_dup_kernel<<<(unsigned)blocks, threads>>>(
        (const float4*)pid, (float4*)out, n4, N / 4, ncopies);

    fixup_kernel<<<(B + 255) / 256, 256>>>(pid, inter, out, B, V, N, ncopies);
}